// round 2
// baseline (speedup 1.0000x reference)
#include <cuda_runtime.h>

// HistogramLayer inference: bias[b] = prod_d hist_probs[bin(b,d), d]
//
// Layout change vs R1: each row is split across a 4-lane group (lane 4r+q
// loads float4 q of row r) so global loads are perfectly coalesced
// (512B per warp LDG.128 instead of 32x16B scattered over 2KB). The
// per-row product is recombined with two shfl.bfly multiplies.
//
// Binning: t = clamp(floor(x/s + 4), 0, 7) candidate (edges[5][d]==scale_d
// bit-exactly since base=linspace(-4,4,9) has base[5]==1.0f), then exact
// +-1 fixup against stored fp32 edges (with +-inf sentinels at the ends):
//   b = t + (x >= e[t+1]) - (x < e[t])
// This matches searchsorted_right semantics bit-exactly.
//
// Shared table s_tab packs (e_t, e_{t+1}, p_t) per (d,t), laid out as
// slot(d,t) = ((d&3)*8 + t)*4 + (d>>2) so the 16B-access bank group is
// (4t + q) mod 8: lanes with different q never conflict; same-q lanes
// conflict at most 2-way.

#define D    16
#define NB   8
#define TPB  256
#define RPT  16
#define ROWS_PER_WARP (8 * RPT)
#define ROWS_PER_BLOCK ((TPB / 32) * ROWS_PER_WARP)

__global__ __launch_bounds__(TPB, 5)
void hist_kernel(const float4* __restrict__ inp4,
                 const float* __restrict__ freq,
                 const float* __restrict__ edges,
                 float* __restrict__ out, int nrows)
{
    __shared__ float4 s_tab[D * NB];       // (lo, hi, p_t, 0), bank-permuted
    __shared__ float  s_p [D * NB];        // probs [d][bin] for rare fixup path
    __shared__ float  s_a [D];             // 1 / scale_d
    __shared__ float  s_e [(NB + 1) * D];  // raw edges staging [j][d]

    const int tid = threadIdx.x;
    if (tid < (NB + 1) * D) s_e[tid] = edges[tid];
    __syncthreads();

    if (tid < D) {
        const int d = tid;
        float ssum = 0.f;
        #pragma unroll
        for (int b = 0; b < NB; ++b) ssum += freq[b * D + d];
        const float inv = 1.0f / ssum;
        float p[NB];
        #pragma unroll
        for (int b = 0; b < NB; ++b) {
            p[b] = freq[b * D + d] * inv;
            s_p[d * NB + b] = p[b];
        }
        const float pinf = __int_as_float(0x7f800000);
        #pragma unroll
        for (int t = 0; t < NB; ++t) {
            const float lo = (t == 0)      ? -pinf : s_e[t * D + d];
            const float hi = (t == NB - 1) ?  pinf : s_e[(t + 1) * D + d];
            s_tab[((d & 3) * NB + t) * 4 + (d >> 2)] = make_float4(lo, hi, p[t], 0.f);
        }
        // base[5] == 1.0f exactly, so edges[5][d] == scale_d bit-exactly.
        s_a[d] = 1.0f / s_e[5 * D + d];
    }
    __syncthreads();

    const int lane = tid & 31;
    const int q    = lane & 3;        // which float4 of the row this lane owns
    const int warp = tid >> 5;

    float av[4];
    #pragma unroll
    for (int i = 0; i < 4; ++i) av[i] = s_a[4 * q + i];

    const long long row0 = (long long)blockIdx.x * ROWS_PER_BLOCK
                         + (long long)warp * ROWS_PER_WARP + (lane >> 2);

    #pragma unroll 4
    for (int s = 0; s < RPT; ++s) {
        const long long row = row0 + s * 8;
        float pr = 1.0f;
        if (row < nrows) {
            // lane address = warp_base*16B + lane*16B -> fully coalesced
            const float4 v = inp4[row * 4 + q];
            const float xs[4] = {v.x, v.y, v.z, v.w};
            #pragma unroll
            for (int i = 0; i < 4; ++i) {
                const float x = xs[i];
                const float y = fmaf(x, av[i], 4.0f);
                int t = __float2int_rd(y);
                t = min(NB - 1, max(0, t));
                const float4 f = s_tab[(i * NB + t) * 4 + q];
                const int b = t + (int)(x >= f.y) - (int)(x < f.x);
                float pb = f.z;
                if (b != t) pb = s_p[(4 * q + i) * NB + b];   // rare (+-1 fixup)
                pr *= pb;
            }
        }
        // product across the 4-lane row group
        pr *= __shfl_xor_sync(0xffffffffu, pr, 1);
        pr *= __shfl_xor_sync(0xffffffffu, pr, 2);
        if (q == 0 && row < nrows) out[row] = pr;
    }
}

extern "C" void kernel_launch(void* const* d_in, const int* in_sizes, int n_in,
                              void* d_out, int out_size)
{
    const float4* inp4 = (const float4*)d_in[0];  // [B, 16] fp32 as [B*4] float4
    const float*  freq = (const float*)d_in[1];   // [8, 16] fp32
    const float*  edges= (const float*)d_in[2];   // [9, 16] fp32
    float* out = (float*)d_out;                   // [B] fp32

    const int nrows = out_size;
    const int grid = (nrows + ROWS_PER_BLOCK - 1) / ROWS_PER_BLOCK;
    hist_kernel<<<grid, TPB>>>(inp4, freq, edges, out, nrows);
}

// round 3
// speedup vs baseline: 1.3627x; 1.3627x over previous
#include <cuda_runtime.h>

// HistogramLayer inference: bias[b] = prod_d hist_probs[bin(b,d), d]
//
// 4 lanes per row (lane q owns float4 q) -> perfectly coalesced LDG.128
// (warp reads 512B contiguous per load). 2 rows per thread per iteration
// for MLP. Row product recombined with two shfl.bfly multiplies.
//
// Binning (bit-exact vs searchsorted_right):
//   base = linspace(-4,4,9) is exact integers, so edges[5][d] == scale_d.
//   a = 1/s (rn). y = fma(x, a, 4 - 1e-4). All rounding terms (fma 0.5ulp,
//   recip 1ulp, edge rounding 0.5ulp) total < 2e-6 in y-units, so with the
//   1e-4 guard folded into the constant, t0 = clamp(floor(y),0,7) satisfies
//   b_true in {t0, t0+1}. Then b = t0 + (e_{t0+1} <= x) is EXACT (searchsorted
//   right counts edges <= x), with +inf sentinel at t0=7 so b never overflows.
//
// Shared tables are stride-1 fp32 arrays laid out [i][8q+t]: at inner step i
// the 32 lanes hit 32 distinct banks -> conflict-free LDS.32 (1 wf each).

#define D    16
#define NB   8
#define TPB  256
#define RPT  16
#define ROWS_PER_WARP (RPT * 16)          // 2 rows/thread/iter * 8 groups
#define ROWS_PER_BLOCK ((TPB / 32) * ROWS_PER_WARP)   // 2048

__global__ __launch_bounds__(TPB)
void hist_kernel(const float4* __restrict__ inp4,
                 const float* __restrict__ freq,
                 const float* __restrict__ edges,
                 float* __restrict__ out, int nrows)
{
    __shared__ float s_hi[4 * 32];        // [i][8q+t] = e_{t+1} of feature 4q+i (+inf at t=7)
    __shared__ float s_p [4 * 32];        // [i][8q+b] = hist_probs[b][4q+i]
    __shared__ float s_a [D];             // 1 / scale_d
    __shared__ float s_e [(NB + 1) * D];  // raw edges staging [j][d]

    const int tid = threadIdx.x;
    if (tid < (NB + 1) * D) s_e[tid] = edges[tid];
    __syncthreads();

    if (tid < D) {
        const int d = tid;
        const int qq = d >> 2, ii = d & 3;
        float ssum = 0.f;
        #pragma unroll
        for (int b = 0; b < NB; ++b) ssum += freq[b * D + d];
        const float pinf = __int_as_float(0x7f800000);
        #pragma unroll
        for (int t = 0; t < NB; ++t) {
            s_p [ii * 32 + qq * 8 + t] = freq[t * D + d] / ssum;
            s_hi[ii * 32 + qq * 8 + t] = (t == NB - 1) ? pinf : s_e[(t + 1) * D + d];
        }
        // base[5] == 1.0f exactly, so edges[5][d] == scale_d bit-exactly.
        s_a[d] = 1.0f / s_e[5 * D + d];
    }
    __syncthreads();

    const int lane = tid & 31;
    const int q    = lane & 3;            // which float4 of the row this lane owns
    const int g    = lane >> 2;           // row-group within warp (0..7)
    const int warp = tid >> 5;
    const int qb   = q * 8;

    float av[4];
    #pragma unroll
    for (int i = 0; i < 4; ++i) av[i] = s_a[4 * q + i];

    const long long wbase = (long long)blockIdx.x * ROWS_PER_BLOCK
                          + (long long)warp * ROWS_PER_WARP;

    const bool full = (wbase + ROWS_PER_WARP) <= (long long)nrows;

    #pragma unroll 2
    for (int it = 0; it < RPT; ++it) {
        const long long r0   = wbase + it * 16;
        const long long rowA = r0 + g;
        const long long rowB = r0 + 8 + g;

        float4 vA = make_float4(0.f, 0.f, 0.f, 0.f);
        float4 vB = vA;
        if (full) {
            vA = inp4[rowA * 4 + q];      // lanes 0..31 -> 512B contiguous
            vB = inp4[rowB * 4 + q];
        } else {
            if (rowA < nrows) vA = inp4[rowA * 4 + q];
            if (rowB < nrows) vB = inp4[rowB * 4 + q];
        }

        float prA = 1.0f, prB = 1.0f;
        {
            const float xsA[4] = {vA.x, vA.y, vA.z, vA.w};
            const float xsB[4] = {vB.x, vB.y, vB.z, vB.w};
            #pragma unroll
            for (int i = 0; i < 4; ++i) {
                const int tb = i * 32 + qb;
                // row A element
                {
                    const float x = xsA[i];
                    const float y = fmaf(x, av[i], 3.9999f);  // 4 - 1e-4 guard
                    int t = __float2int_rd(y);
                    t = min(NB - 1, max(t, 0));
                    const int idx = tb + t;
                    const float hi = s_hi[idx];
                    const int b = idx + (x >= hi ? 1 : 0);
                    prA *= s_p[b];
                }
                // row B element
                {
                    const float x = xsB[i];
                    const float y = fmaf(x, av[i], 3.9999f);
                    int t = __float2int_rd(y);
                    t = min(NB - 1, max(t, 0));
                    const int idx = tb + t;
                    const float hi = s_hi[idx];
                    const int b = idx + (x >= hi ? 1 : 0);
                    prB *= s_p[b];
                }
            }
        }
        // product across the 4-lane row group
        prA *= __shfl_xor_sync(0xffffffffu, prA, 1);
        prA *= __shfl_xor_sync(0xffffffffu, prA, 2);
        prB *= __shfl_xor_sync(0xffffffffu, prB, 1);
        prB *= __shfl_xor_sync(0xffffffffu, prB, 2);

        if (q == 0) {
            if (full) {
                out[rowA] = prA;          // 8 lanes -> 32B contiguous
                out[rowB] = prB;
            } else {
                if (rowA < nrows) out[rowA] = prA;
                if (rowB < nrows) out[rowB] = prB;
            }
        }
    }
}

extern "C" void kernel_launch(void* const* d_in, const int* in_sizes, int n_in,
                              void* d_out, int out_size)
{
    const float4* inp4 = (const float4*)d_in[0];  // [B, 16] fp32 as [B*4] float4
    const float*  freq = (const float*)d_in[1];   // [8, 16] fp32
    const float*  edges= (const float*)d_in[2];   // [9, 16] fp32
    float* out = (float*)d_out;                   // [B] fp32

    const int nrows = out_size;
    const int grid = (nrows + ROWS_PER_BLOCK - 1) / ROWS_PER_BLOCK;
    hist_kernel<<<grid, TPB>>>(inp4, freq, edges, out, nrows);
}

// round 9
// speedup vs baseline: 1.7540x; 1.2871x over previous
#include <cuda_runtime.h>

// HistogramLayer inference: bias[b] = prod_d hist_probs[bin(b,d), d]
//
// Split-lane layout: lane l = 4g+q owns float4-chunk q; per iteration the
// warp loads a 32-row tile as 4 fully-coalesced LDG.128 (lane l reads
// float4 tile_base + 32k + l), so lane l holds chunk q of rows
// {g, g+8, g+16, g+24}. Each lane bins its 4 features for 4 rows; the row
// product is recombined with two shfl.bfly multiplies; q==0 lanes store.
//
// Binning (bit-exact vs searchsorted_right): base=linspace(-4,4,9) is exact
// integers so edges[5][d]==scale_d bit-exactly. y = fma(x, 1/s, 4-1e-4),
// total fp error in y < 2e-6 << 1e-4 guard, so t = floor(clamp(y,0,7.49))
// satisfies b_true in {t, t+1}, resolved EXACTLY by the stored-edge test
// b = t + (x >= e_{t+1}) (+inf sentinel at t=7; clamped ends are fixup-free
// by construction). Implemented branch-free as a select between p_t and
// p_{t+1}.
//
// Shared tables are stride-1 fp32 arrays indexed idx = i*32 + q*8 + t:
// within any warp step, idx mod 32 = q*8+t covers 32 distinct banks
// (duplicates broadcast) -> conflict-free LDS.32.
//
// NO divergent branches, NO warp sync intrinsics beyond shfl, single
// top-level warp-uniform full/tail branch.

#define D    16
#define NB   8
#define TPB  256
#define RPT  8
#define ROWS_PER_WARP  (RPT * 32)                      // 256
#define ROWS_PER_BLOCK ((TPB / 32) * ROWS_PER_WARP)    // 2048

__global__ __launch_bounds__(TPB)
void hist_kernel(const float4* __restrict__ inp4,
                 const float* __restrict__ freq,
                 const float* __restrict__ edges,
                 float* __restrict__ out, int nrows)
{
    __shared__ float s_hi[4 * 32];        // [i][8q+t] = e_{t+1} (+inf at t=7)
    __shared__ float s_pt[4 * 32];        // [i][8q+t] = p_t (idx+1 = p_{t+1}, t<=6)
    __shared__ float s_a [D];             // 1 / scale_d
    __shared__ float s_e [(NB + 1) * D];  // raw edges staging [j][d]

    const int tid = threadIdx.x;
    if (tid < (NB + 1) * D) s_e[tid] = edges[tid];
    __syncthreads();

    if (tid < D) {
        const int d = tid;
        const int slot = (d & 3) * 32 + (d >> 2) * 8;   // i*32 + q*8
        float ssum = 0.f;
        #pragma unroll
        for (int b = 0; b < NB; ++b) ssum += freq[b * D + d];
        const float inv  = 1.0f / ssum;
        const float pinf = __int_as_float(0x7f800000);
        #pragma unroll
        for (int t = 0; t < NB; ++t) {
            s_pt[slot + t] = freq[t * D + d] * inv;
            s_hi[slot + t] = (t == NB - 1) ? pinf : s_e[(t + 1) * D + d];
        }
        s_a[d] = 1.0f / s_e[5 * D + d];   // edges[5][d] == scale_d bit-exactly
    }
    __syncthreads();

    const int lane = tid & 31;
    const int q    = lane & 3;
    const int g    = lane >> 2;
    const int warp = tid >> 5;
    const int qb   = q * 8;

    float av[4];
    #pragma unroll
    for (int i = 0; i < 4; ++i) av[i] = s_a[4 * q + i];

    const int wbase = blockIdx.x * ROWS_PER_BLOCK + warp * ROWS_PER_WARP;
    const float4* p4 = inp4 + (unsigned)wbase * 4 + lane;  // coalesced base

    if (wbase + ROWS_PER_WARP <= nrows) {
        // ---------- full tile: branch-free hot loop ----------
        #pragma unroll 1
        for (int it = 0; it < RPT; ++it) {
            float4 v[4];
            #pragma unroll
            for (int k = 0; k < 4; ++k) v[k] = p4[it * 128 + k * 32];

            float pr[4] = {1.f, 1.f, 1.f, 1.f};
            #pragma unroll
            for (int i = 0; i < 4; ++i) {
                const int tb = i * 32 + qb;
                #pragma unroll
                for (int k = 0; k < 4; ++k) {
                    const float x = (i == 0) ? v[k].x : (i == 1) ? v[k].y
                                  : (i == 2) ? v[k].z : v[k].w;
                    float y = fmaf(x, av[i], 3.9999f);        // 4 - 1e-4
                    y = fminf(fmaxf(y, 0.0f), 7.49f);
                    const int idx = tb + __float2int_rd(y);
                    const float hi = s_hi[idx];
                    const float p0 = s_pt[idx];
                    const float p1 = s_pt[idx + (x >= hi ? 1 : 0)];
                    pr[k] *= (x >= hi) ? p1 : p0;
                }
            }
            #pragma unroll
            for (int k = 0; k < 4; ++k) {
                pr[k] *= __shfl_xor_sync(0xffffffffu, pr[k], 1);
                pr[k] *= __shfl_xor_sync(0xffffffffu, pr[k], 2);
            }
            if (q == 0) {
                const int r0 = wbase + it * 32 + g;
                #pragma unroll
                for (int k = 0; k < 4; ++k) out[r0 + 8 * k] = pr[k];
            }
        }
    } else {
        // ---------- tail tile: guarded (rarely/never taken) ----------
        #pragma unroll 1
        for (int it = 0; it < RPT; ++it) {
            float4 v[4];
            #pragma unroll
            for (int k = 0; k < 4; ++k) {
                const int row = wbase + it * 32 + 8 * k + g;
                v[k] = (row < nrows) ? p4[it * 128 + k * 32]
                                     : make_float4(0.f, 0.f, 0.f, 0.f);
            }
            float pr[4] = {1.f, 1.f, 1.f, 1.f};
            #pragma unroll
            for (int i = 0; i < 4; ++i) {
                const int tb = i * 32 + qb;
                #pragma unroll
                for (int k = 0; k < 4; ++k) {
                    const float x = (i == 0) ? v[k].x : (i == 1) ? v[k].y
                                  : (i == 2) ? v[k].z : v[k].w;
                    float y = fmaf(x, av[i], 3.9999f);
                    y = fminf(fmaxf(y, 0.0f), 7.49f);
                    const int idx = tb + __float2int_rd(y);
                    const float hi = s_hi[idx];
                    const float p0 = s_pt[idx];
                    const float p1 = s_pt[idx + (x >= hi ? 1 : 0)];
                    pr[k] *= (x >= hi) ? p1 : p0;
                }
            }
            #pragma unroll
            for (int k = 0; k < 4; ++k) {
                pr[k] *= __shfl_xor_sync(0xffffffffu, pr[k], 1);
                pr[k] *= __shfl_xor_sync(0xffffffffu, pr[k], 2);
            }
            if (q == 0) {
                const int r0 = wbase + it * 32 + g;
                #pragma unroll
                for (int k = 0; k < 4; ++k)
                    if (r0 + 8 * k < nrows) out[r0 + 8 * k] = pr[k];
            }
        }
    }
}

extern "C" void kernel_launch(void* const* d_in, const int* in_sizes, int n_in,
                              void* d_out, int out_size)
{
    const float4* inp4 = (const float4*)d_in[0];  // [B,16] fp32 = float4[B*4]
    const float*  freq = (const float*)d_in[1];   // [8,16] fp32
    const float*  edges= (const float*)d_in[2];   // [9,16] fp32
    float* out = (float*)d_out;                   // [B] fp32

    const int nrows = out_size;
    const int grid = (nrows + ROWS_PER_BLOCK - 1) / ROWS_PER_BLOCK;
    hist_kernel<<<grid, TPB>>>(inp4, freq, edges, out, nrows);
}

// round 10
// speedup vs baseline: 1.8390x; 1.0485x over previous
#include <cuda_runtime.h>

// HistogramLayer inference: bias[b] = prod_d hist_probs[bin(b,d), d]
//
// Split-lane layout: lane l = 4g+q owns float4-chunk q; per iteration the
// warp loads a 32-row tile as 4 fully-coalesced LDG.128 (lane l reads
// float4 tile_base + 32k + l), so lane l holds chunk q of rows
// {g, g+8, g+16, g+24}. Each lane bins its 4 features for 4 rows; the row
// product is recombined with two shfl.bfly multiplies; q==0 lanes store.
//
// Binning (bit-exact vs searchsorted_right): base=linspace(-4,4,9) is exact
// integers so edges[5][d]==scale_d bit-exactly. y = fma(x, 1/s, 4-1e-4),
// total fp error in y < 2e-6 << 1e-4 guard, so t = floor(clamp(y,0,7.49))
// satisfies b_true in {t, t+1}, resolved EXACTLY by the stored-edge test
// b = t + (x >= e_{t+1}) (+inf sentinel at t=7 means the +1 never fires
// there, so idx+1 never crosses a feature boundary; clamped ends are
// fixup-free by construction). ONE probability LDS per element:
// pb = s_pt[idx + (x >= hi)].
//
// Shared tables are stride-1 fp32 arrays indexed idx = i*32 + q*8 + t:
// within any warp step, idx mod 32 = q*8+t covers 32 distinct banks
// (duplicates broadcast) -> conflict-free LDS.32.

#define D    16
#define NB   8
#define TPB  256
#define RPT  8
#define ROWS_PER_WARP  (RPT * 32)                      // 256
#define ROWS_PER_BLOCK ((TPB / 32) * ROWS_PER_WARP)    // 2048

__global__ __launch_bounds__(TPB)
void hist_kernel(const float4* __restrict__ inp4,
                 const float* __restrict__ freq,
                 const float* __restrict__ edges,
                 float* __restrict__ out, int nrows)
{
    __shared__ float s_hi[4 * 32];        // [i][8q+t] = e_{t+1} (+inf at t=7)
    __shared__ float s_pt[4 * 32 + 1];    // [i][8q+t] = p_t (+1 pad, never read)
    __shared__ float s_a [D];             // 1 / scale_d
    __shared__ float s_e [(NB + 1) * D];  // raw edges staging [j][d]

    const int tid = threadIdx.x;
    if (tid < (NB + 1) * D) s_e[tid] = edges[tid];
    __syncthreads();

    if (tid < D) {
        const int d = tid;
        const int slot = (d & 3) * 32 + (d >> 2) * 8;   // i*32 + q*8
        float ssum = 0.f;
        #pragma unroll
        for (int b = 0; b < NB; ++b) ssum += freq[b * D + d];
        const float inv  = 1.0f / ssum;
        const float pinf = __int_as_float(0x7f800000);
        #pragma unroll
        for (int t = 0; t < NB; ++t) {
            s_pt[slot + t] = freq[t * D + d] * inv;
            s_hi[slot + t] = (t == NB - 1) ? pinf : s_e[(t + 1) * D + d];
        }
        s_a[d] = 1.0f / s_e[5 * D + d];   // edges[5][d] == scale_d bit-exactly
    }
    if (tid == 0) s_pt[4 * 32] = 0.f;
    __syncthreads();

    const int lane = tid & 31;
    const int q    = lane & 3;
    const int g    = lane >> 2;
    const int warp = tid >> 5;
    const int qb   = q * 8;

    float av[4];
    #pragma unroll
    for (int i = 0; i < 4; ++i) av[i] = s_a[4 * q + i];

    const int wbase = blockIdx.x * ROWS_PER_BLOCK + warp * ROWS_PER_WARP;
    const float4* p4 = inp4 + (unsigned)wbase * 4 + lane;  // coalesced base

    if (wbase + ROWS_PER_WARP <= nrows) {
        // ---------- full tile: branch-free hot loop ----------
        #pragma unroll 1
        for (int it = 0; it < RPT; ++it) {
            float4 v[4];
            #pragma unroll
            for (int k = 0; k < 4; ++k) v[k] = __ldcs(&p4[it * 128 + k * 32]);

            float pr[4] = {1.f, 1.f, 1.f, 1.f};
            #pragma unroll
            for (int i = 0; i < 4; ++i) {
                const int tb = i * 32 + qb;
                #pragma unroll
                for (int k = 0; k < 4; ++k) {
                    const float x = (i == 0) ? v[k].x : (i == 1) ? v[k].y
                                  : (i == 2) ? v[k].z : v[k].w;
                    float y = fmaf(x, av[i], 3.9999f);        // 4 - 1e-4
                    y = fminf(fmaxf(y, 0.0f), 7.49f);
                    const int idx = tb + __float2int_rd(y);
                    const float hi = s_hi[idx];
                    pr[k] *= s_pt[idx + ((x >= hi) ? 1 : 0)];
                }
            }
            #pragma unroll
            for (int k = 0; k < 4; ++k) {
                pr[k] *= __shfl_xor_sync(0xffffffffu, pr[k], 1);
                pr[k] *= __shfl_xor_sync(0xffffffffu, pr[k], 2);
            }
            if (q == 0) {
                const int r0 = wbase + it * 32 + g;
                #pragma unroll
                for (int k = 0; k < 4; ++k) __stcs(&out[r0 + 8 * k], pr[k]);
            }
        }
    } else {
        // ---------- tail tile: guarded (rarely/never taken) ----------
        #pragma unroll 1
        for (int it = 0; it < RPT; ++it) {
            float4 v[4];
            #pragma unroll
            for (int k = 0; k < 4; ++k) {
                const int row = wbase + it * 32 + 8 * k + g;
                v[k] = (row < nrows) ? p4[it * 128 + k * 32]
                                     : make_float4(0.f, 0.f, 0.f, 0.f);
            }
            float pr[4] = {1.f, 1.f, 1.f, 1.f};
            #pragma unroll
            for (int i = 0; i < 4; ++i) {
                const int tb = i * 32 + qb;
                #pragma unroll
                for (int k = 0; k < 4; ++k) {
                    const float x = (i == 0) ? v[k].x : (i == 1) ? v[k].y
                                  : (i == 2) ? v[k].z : v[k].w;
                    float y = fmaf(x, av[i], 3.9999f);
                    y = fminf(fmaxf(y, 0.0f), 7.49f);
                    const int idx = tb + __float2int_rd(y);
                    const float hi = s_hi[idx];
                    pr[k] *= s_pt[idx + ((x >= hi) ? 1 : 0)];
                }
            }
            #pragma unroll
            for (int k = 0; k < 4; ++k) {
                pr[k] *= __shfl_xor_sync(0xffffffffu, pr[k], 1);
                pr[k] *= __shfl_xor_sync(0xffffffffu, pr[k], 2);
            }
            if (q == 0) {
                const int r0 = wbase + it * 32 + g;
                #pragma unroll
                for (int k = 0; k < 4; ++k)
                    if (r0 + 8 * k < nrows) out[r0 + 8 * k] = pr[k];
            }
        }
    }
}

extern "C" void kernel_launch(void* const* d_in, const int* in_sizes, int n_in,
                              void* d_out, int out_size)
{
    const float4* inp4 = (const float4*)d_in[0];  // [B,16] fp32 = float4[B*4]
    const float*  freq = (const float*)d_in[1];   // [8,16] fp32
    const float*  edges= (const float*)d_in[2];   // [9,16] fp32
    float* out = (float*)d_out;                   // [B] fp32

    const int nrows = out_size;
    const int grid = (nrows + ROWS_PER_BLOCK - 1) / ROWS_PER_BLOCK;
    hist_kernel<<<grid, TPB>>>(inp4, freq, edges, out, nrows);
}

// round 11
// speedup vs baseline: 1.9016x; 1.0340x over previous
#include <cuda_runtime.h>

// HistogramLayer inference: bias[b] = prod_d hist_probs[bin(b,d), d]
//
// Split-lane layout: lane l = 4g+q owns float4-chunk q. Per iteration the
// warp loads a 64-row tile as 8 batched fully-coalesced LDG.128 (MLP=8),
// so lane l holds chunk q of rows {g, g+8, ..., g+56}. Each lane bins its
// 4 features for 8 rows; row products recombine via two shfl.bfly
// multiplies; q==0 lanes store.
//
// Binning (bit-exact vs searchsorted_right): base=linspace(-4,4,9) is exact
// integers so edges[5][d]==scale_d bit-exactly. Let
//   z  = saturate(fma(x, (1/s)/8, (4 - 1e-4)/8))      (SAT folds into FFMA)
//   t4 = floor(z * 31.996) & ~3                        (= 4 * bin candidate)
// Downward shift of the implied y = x/s + 4 is <= 1e-4 (guard) + 1e-3
// (31.996-vs-32 scale) + 2e-6 (fp rounding) < 1 bin, and y is never
// overshot, so b_true in {t, t+1}; resolved EXACTLY by the stored-edge
// test b = t + (x >= e_{t+1}) (+inf sentinel at t=7 so the +1 never
// crosses a feature boundary; clamped ends are fixup-free). ONE
// probability LDS per element: pb = s_pt[idx + (x >= hi)].
//
// Shared tables are stride-1 fp32, byte-indexed tb4 + t4 with
// tb4 = i*128 + q*32: within any warp step the 32 lanes cover 32 distinct
// banks (duplicates broadcast) -> conflict-free LDS.32.

#define D    16
#define NB   8
#define TPB  256
#define RPT  4
#define ROWS_PER_WARP  (RPT * 64)                      // 256
#define ROWS_PER_BLOCK ((TPB / 32) * ROWS_PER_WARP)    // 2048

__global__ __launch_bounds__(TPB)
void hist_kernel(const float4* __restrict__ inp4,
                 const float* __restrict__ freq,
                 const float* __restrict__ edges,
                 float* __restrict__ out, int nrows)
{
    __shared__ float s_hi[4 * 32];        // [i][8q+t] = e_{t+1} (+inf at t=7)
    __shared__ float s_pt[4 * 32 + 1];    // [i][8q+t] = p_t (+1 pad, never read)
    __shared__ float s_a [D];             // (1/scale_d) / 8
    __shared__ float s_e [(NB + 1) * D];  // raw edges staging [j][d]

    const int tid = threadIdx.x;
    if (tid < (NB + 1) * D) s_e[tid] = edges[tid];
    __syncthreads();

    if (tid < D) {
        const int d = tid;
        const int slot = (d & 3) * 32 + (d >> 2) * 8;   // i*32 + q*8
        float ssum = 0.f;
        #pragma unroll
        for (int b = 0; b < NB; ++b) ssum += freq[b * D + d];
        const float inv  = 1.0f / ssum;
        const float pinf = __int_as_float(0x7f800000);
        #pragma unroll
        for (int t = 0; t < NB; ++t) {
            s_pt[slot + t] = freq[t * D + d] * inv;
            s_hi[slot + t] = (t == NB - 1) ? pinf : s_e[(t + 1) * D + d];
        }
        // edges[5][d] == scale_d bit-exactly; /8 is an exact exponent shift
        s_a[d] = (1.0f / s_e[5 * D + d]) * 0.125f;
    }
    if (tid == 0) s_pt[4 * 32] = 0.f;
    __syncthreads();

    const int lane = tid & 31;
    const int q    = lane & 3;
    const int g    = lane >> 2;
    const int warp = tid >> 5;
    const int qb4  = q * 32;              // byte offset of this lane's q-block

    float av[4];
    #pragma unroll
    for (int i = 0; i < 4; ++i) av[i] = s_a[4 * q + i];

    const int wbase = blockIdx.x * ROWS_PER_BLOCK + warp * ROWS_PER_WARP;
    const float4* p4 = inp4 + (unsigned)wbase * 4 + lane;  // coalesced base

    const char* chi = (const char*)s_hi;
    const char* cpt = (const char*)s_pt;

    if (wbase + ROWS_PER_WARP <= nrows) {
        // ---------- full tile: branch-free hot loop, 8 loads in flight ----
        #pragma unroll 1
        for (int it = 0; it < RPT; ++it) {
            float4 v[8];
            #pragma unroll
            for (int k = 0; k < 8; ++k) v[k] = __ldcs(&p4[it * 256 + k * 32]);

            float pr[8] = {1.f, 1.f, 1.f, 1.f, 1.f, 1.f, 1.f, 1.f};
            #pragma unroll
            for (int i = 0; i < 4; ++i) {
                const int tb4 = i * 128 + qb4;
                #pragma unroll
                for (int k = 0; k < 8; ++k) {
                    const float x = (i == 0) ? v[k].x : (i == 1) ? v[k].y
                                  : (i == 2) ? v[k].z : v[k].w;
                    const float z = __saturatef(fmaf(x, av[i], 0.49998750f));
                    const int t4 = __float2int_rd(z * 31.996f) & ~3;
                    const float hi = *(const float*)(chi + tb4 + t4);
                    const int s4 = (x >= hi) ? 4 : 0;
                    pr[k] *= *(const float*)(cpt + tb4 + t4 + s4);
                }
            }
            #pragma unroll
            for (int k = 0; k < 8; ++k) {
                pr[k] *= __shfl_xor_sync(0xffffffffu, pr[k], 1);
                pr[k] *= __shfl_xor_sync(0xffffffffu, pr[k], 2);
            }
            if (q == 0) {
                const int r0 = wbase + it * 64 + g;
                #pragma unroll
                for (int k = 0; k < 8; ++k) __stcs(&out[r0 + 8 * k], pr[k]);
            }
        }
    } else {
        // ---------- tail tile: guarded (never taken when B % 2048 == 0) ---
        #pragma unroll 1
        for (int it = 0; it < RPT; ++it) {
            float4 v[8];
            #pragma unroll
            for (int k = 0; k < 8; ++k) {
                const int row = wbase + it * 64 + 8 * k + g;
                v[k] = (row < nrows) ? p4[it * 256 + k * 32]
                                     : make_float4(0.f, 0.f, 0.f, 0.f);
            }
            float pr[8] = {1.f, 1.f, 1.f, 1.f, 1.f, 1.f, 1.f, 1.f};
            #pragma unroll
            for (int i = 0; i < 4; ++i) {
                const int tb4 = i * 128 + qb4;
                #pragma unroll
                for (int k = 0; k < 8; ++k) {
                    const float x = (i == 0) ? v[k].x : (i == 1) ? v[k].y
                                  : (i == 2) ? v[k].z : v[k].w;
                    const float z = __saturatef(fmaf(x, av[i], 0.49998750f));
                    const int t4 = __float2int_rd(z * 31.996f) & ~3;
                    const float hi = *(const float*)(chi + tb4 + t4);
                    const int s4 = (x >= hi) ? 4 : 0;
                    pr[k] *= *(const float*)(cpt + tb4 + t4 + s4);
                }
            }
            #pragma unroll
            for (int k = 0; k < 8; ++k) {
                pr[k] *= __shfl_xor_sync(0xffffffffu, pr[k], 1);
                pr[k] *= __shfl_xor_sync(0xffffffffu, pr[k], 2);
            }
            if (q == 0) {
                const int r0 = wbase + it * 64 + g;
                #pragma unroll
                for (int k = 0; k < 8; ++k)
                    if (r0 + 8 * k < nrows) out[r0 + 8 * k] = pr[k];
            }
        }
    }
}

extern "C" void kernel_launch(void* const* d_in, const int* in_sizes, int n_in,
                              void* d_out, int out_size)
{
    const float4* inp4 = (const float4*)d_in[0];  // [B,16] fp32 = float4[B*4]
    const float*  freq = (const float*)d_in[1];   // [8,16] fp32
    const float*  edges= (const float*)d_in[2];   // [9,16] fp32
    float* out = (float*)d_out;                   // [B] fp32

    const int nrows = out_size;
    const int grid = (nrows + ROWS_PER_BLOCK - 1) / ROWS_PER_BLOCK;
    hist_kernel<<<grid, TPB>>>(inp4, freq, edges, out, nrows);
}